// round 6
// baseline (speedup 1.0000x reference)
#include <cuda_runtime.h>
#include <cuda_bf16.h>
#include <cstdint>

#define MAX_N 100000
#define MAX_E 1600000
#define SCAN_B 1024

// ---------------- static scratch: addresses taken ONLY in device code ----------
__device__ __align__(16) float g_msg[MAX_N * 64];
__device__ __align__(16) float g_h1 [MAX_N * 64];
__device__ __align__(16) float g_h2 [MAX_N * 64];
__device__ __align__(16) float g_h3 [MAX_N * 32];
__device__ __align__(16) int   g_deg [MAX_N];
__device__ __align__(16) int   g_part[MAX_N];
__device__ __align__(16) int   g_bsum[128];
__device__ __align__(16) int   g_offs[MAX_N + 1];
__device__ __align__(16) int   g_cur [MAX_N];
__device__ __align__(16) int   g_elist[MAX_E];

// buffer tag: 1 -> g_h1, 2 -> g_h2 (0 means "use external pointer")
__device__ __forceinline__ const float* pick_src(const float* ext, int tag) {
    if (tag == 1) return g_h1;
    if (tag == 2) return g_h2;
    return ext;
}
__device__ __forceinline__ float* pick_dst64(int tag) {
    return (tag == 1) ? g_h1 : g_h2;
}

// ---------------- CSR build ----------------------------------------------------
__global__ void k_zero2(int n) {
    int i = blockIdx.x * blockDim.x + threadIdx.x;
    if (i < n) { g_deg[i] = 0; g_cur[i] = 0; }
}

// edge_index is INT32 on the wire (JAX x64 disabled): row0 = src, row1 = dst.
__global__ void k_count(const int* __restrict__ ei, int nE) {
    int e = blockIdx.x * blockDim.x + threadIdx.x;
    if (e < nE) atomicAdd(&g_deg[ei[nE + e]], 1);
}

__global__ void k_scanA(int n) {
    __shared__ int sm[SCAN_B];
    int i = blockIdx.x * SCAN_B + threadIdx.x;
    sm[threadIdx.x] = (i < n) ? g_deg[i] : 0;
    __syncthreads();
    for (int off = 1; off < SCAN_B; off <<= 1) {
        int t = 0;
        if (threadIdx.x >= off) t = sm[threadIdx.x - off];
        __syncthreads();
        if (threadIdx.x >= off) sm[threadIdx.x] += t;
        __syncthreads();
    }
    if (i < n) g_part[i] = sm[threadIdx.x];
    if (threadIdx.x == SCAN_B - 1) g_bsum[blockIdx.x] = sm[SCAN_B - 1];
}

__global__ void k_scanB(int nb) {              // 1 block, 128 threads
    __shared__ int sm[128];
    int v = (threadIdx.x < nb) ? g_bsum[threadIdx.x] : 0;
    sm[threadIdx.x] = v;
    __syncthreads();
    for (int off = 1; off < 128; off <<= 1) {
        int t = 0;
        if (threadIdx.x >= off) t = sm[threadIdx.x - off];
        __syncthreads();
        if (threadIdx.x >= off) sm[threadIdx.x] += t;
        __syncthreads();
    }
    if (threadIdx.x < nb) g_bsum[threadIdx.x] = sm[threadIdx.x] - v;  // exclusive
}

__global__ void k_scanC(int n) {
    int i = blockIdx.x * blockDim.x + threadIdx.x;
    if (i < n) g_offs[i + 1] = g_part[i] + g_bsum[i / SCAN_B];
    if (i == 0) g_offs[0] = 0;
}

__global__ void k_fill(const int* __restrict__ ei, int nE) {
    int e = blockIdx.x * blockDim.x + threadIdx.x;
    if (e >= nE) return;
    int s = ei[e];
    int d = ei[nE + e];
    int slot = g_offs[d] + atomicAdd(&g_cur[d], 1);
    g_elist[slot] = s;
}

// ---------------- gather-aggregate: g_msg[n] = mean of src[neighbors] ---------
// One warp per node; lane L owns features [2L, 2L+1]. No float atomics.
__global__ void k_agg(const float* __restrict__ xin_ext, int src_tag, int n) {
    int w = (blockIdx.x * blockDim.x + threadIdx.x) >> 5;
    int lane = threadIdx.x & 31;
    if (w >= n) return;
    const float* __restrict__ xin = pick_src(xin_ext, src_tag);
    int start = g_offs[w];
    int end   = g_offs[w + 1];
    const float2* __restrict__ base = (const float2*)xin;
    float ax = 0.f, ay = 0.f;
    int i = start;
    for (; i + 4 <= end; i += 4) {
        int s0 = g_elist[i];
        int s1 = g_elist[i + 1];
        int s2 = g_elist[i + 2];
        int s3 = g_elist[i + 3];
        float2 v0 = base[(size_t)s0 * 32 + lane];
        float2 v1 = base[(size_t)s1 * 32 + lane];
        float2 v2 = base[(size_t)s2 * 32 + lane];
        float2 v3 = base[(size_t)s3 * 32 + lane];
        ax += v0.x + v1.x + v2.x + v3.x;
        ay += v0.y + v1.y + v2.y + v3.y;
    }
    for (; i < end; i++) {
        float2 v = base[(size_t)g_elist[i] * 32 + lane];
        ax += v.x; ay += v.y;
    }
    float invd = 1.0f / fmaxf((float)(end - start), 1.0f);
    float2 o; o.x = ax * invd; o.y = ay * invd;
    ((float2*)g_msg)[(size_t)w * 32 + lane] = o;
}

// ---------------- dense: dst = relu(mean@Wl.T + b + x@Wr.T) --------------------
// Two K=64 phases over one 64-node tile; static smem <= 48KB; 4x4 register tile.
template<int DOUT>
__global__ void k_dense(const float* __restrict__ xin_ext, int src_tag, int dst_tag,
                        const float* __restrict__ Wl, const float* __restrict__ Wr,
                        const float* __restrict__ bias, int nNodes)
{
    constexpr int BS = DOUT + 4;
    constexpr int AS = 68;
    __shared__ float sB[64 * BS];
    __shared__ float sA[64 * AS];

    const float* __restrict__ xin = pick_src(xin_ext, src_tag);
    float* __restrict__ outp = (DOUT == 32) ? g_h3 : pick_dst64(dst_tag);

    const int tid = threadIdx.x;
    const int nT = (DOUT / 4) * 16;
    const int tx = tid % (DOUT / 4);
    const int ty = tid / (DOUT / 4);
    const int node0 = blockIdx.x * 64;

    float acc[4][4];
#pragma unroll
    for (int j = 0; j < 4; j++) {
        float bv = bias[tx * 4 + j];
#pragma unroll
        for (int i = 0; i < 4; i++) acc[i][j] = bv;
    }

#pragma unroll
    for (int phase = 0; phase < 2; phase++) {
        const float* __restrict__ W   = phase ? Wr : Wl;
        const float* __restrict__ src = phase ? xin : g_msg;

        for (int idx = tid; idx < 64 * DOUT; idx += nT) {
            int k = idx & 63;
            int o = idx >> 6;
            sB[k * BS + o] = W[o * 64 + k];          // transpose into smem
        }
        for (int idx = tid; idx < 64 * 64; idx += nT) {
            int k = idx & 63;
            int n = idx >> 6;
            int gn = node0 + n;
            sA[n * AS + k] = (gn < nNodes) ? src[(size_t)gn * 64 + k] : 0.f;
        }
        __syncthreads();

#pragma unroll 4
        for (int k = 0; k < 64; k++) {
            float4 b4 = *(const float4*)(&sB[k * BS + tx * 4]);
#pragma unroll
            for (int i = 0; i < 4; i++) {
                float a = sA[(ty * 4 + i) * AS + k];
                acc[i][0] += a * b4.x;
                acc[i][1] += a * b4.y;
                acc[i][2] += a * b4.z;
                acc[i][3] += a * b4.w;
            }
        }
        __syncthreads();
    }

#pragma unroll
    for (int i = 0; i < 4; i++) {
        int gn = node0 + ty * 4 + i;
        if (gn < nNodes) {
            float4 v;
            v.x = fmaxf(acc[i][0], 0.f);
            v.y = fmaxf(acc[i][1], 0.f);
            v.z = fmaxf(acc[i][2], 0.f);
            v.w = fmaxf(acc[i][3], 0.f);
            *(float4*)(&outp[(size_t)gn * DOUT + tx * 4]) = v;
        }
    }
}

// ---------------- regression head: out[n] = g_h3[n]·Wreg + breg ---------------
__global__ void k_head(const float* __restrict__ Wreg, const float* __restrict__ breg,
                       float* __restrict__ out, int n) {
    int i = blockIdx.x * blockDim.x + threadIdx.x;
    if (i >= n) return;
    float acc = breg[0];
    const float4* hr = (const float4*)(g_h3 + (size_t)i * 32);
    const float4* wr = (const float4*)Wreg;
#pragma unroll
    for (int c = 0; c < 8; c++) {
        float4 hv = hr[c];
        float4 wv = wr[c];
        acc += hv.x * wv.x + hv.y * wv.y + hv.z * wv.z + hv.w * wv.w;
    }
    out[i] = acc;
}

// ---------------- launch: kernel launches ONLY ---------------------------------
extern "C" void kernel_launch(void* const* d_in, const int* in_sizes, int n_in,
                              void* d_out, int out_size) {
    const float* x    = (const float*)d_in[0];
    const int*   ei   = (const int*)d_in[1];          // int32! (JAX x64 disabled)
    const float* W1l  = (const float*)d_in[2];
    const float* b1   = (const float*)d_in[3];
    const float* W1r  = (const float*)d_in[4];
    const float* W2l  = (const float*)d_in[5];
    const float* b2   = (const float*)d_in[6];
    const float* W2r  = (const float*)d_in[7];
    const float* W3l  = (const float*)d_in[8];
    const float* b3   = (const float*)d_in[9];
    const float* W3r  = (const float*)d_in[10];
    const float* Wreg = (const float*)d_in[11];
    const float* breg = (const float*)d_in[12];
    float* out = (float*)d_out;

    const int N  = in_sizes[0] / 64;
    const int nE = in_sizes[1] / 2;

    const int TPB = 256;
    const int ebl = (nE + TPB - 1) / TPB;
    const int nbl = (N + TPB - 1) / TPB;
    const int sbl = (N + SCAN_B - 1) / SCAN_B;
    const int dbl = (N + 63) / 64;
    const int abl = (N + 7) / 8;          // 8 warps per 256-thread block

    // CSR build
    k_zero2<<<nbl, TPB>>>(N);
    k_count<<<ebl, TPB>>>(ei, nE);
    k_scanA<<<sbl, SCAN_B>>>(N);
    k_scanB<<<1, 128>>>(sbl);
    k_scanC<<<nbl, TPB>>>(N);
    k_fill<<<ebl, TPB>>>(ei, nE);

    // layer 1: src = external x, dst = g_h1
    k_agg<<<abl, TPB>>>(x, 0, N);
    k_dense<64><<<dbl, 256>>>(x, 0, 1, W1l, W1r, b1, N);
    // layer 2: src = g_h1, dst = g_h2
    k_agg<<<abl, TPB>>>(nullptr, 1, N);
    k_dense<64><<<dbl, 256>>>(nullptr, 1, 2, W2l, W2r, b2, N);
    // layer 3: src = g_h2, dst = g_h3
    k_agg<<<abl, TPB>>>(nullptr, 2, N);
    k_dense<32><<<dbl, 128>>>(nullptr, 2, 3, W3l, W3r, b3, N);
    // head
    k_head<<<nbl, TPB>>>(Wreg, breg, out, N);
}